// round 10
// baseline (speedup 1.0000x reference)
#include <cuda_runtime.h>
#include <math.h>
#include <stdint.h>
#include <float.h>

#define NB 16
#define NC 64
#define NH 128
#define NW 128
#define NK 512
#define ND 64
#define NHW (NH*NW)            // 16384
#define NTOK (NB*NHW)          // 262144
#define QELEMS (NB*NC*NHW)     // 1048576
#define OFF_LOSS 0
#define OFF_Q 1
#define OFF_PERP (1 + QELEMS)
#define OFF_ENC (2 + QELEMS)
#define ENC_F ((long long)NTOK * NK)
#define ENC_V4 ((ENC_F - 4) / 4)

#define THR 1.2e-3f            // certainty threshold (>= 2x tf32 distance error)

__device__ unsigned  g_et32[NK * ND];   // tf32 codes, k-pair permuted [code][perm(d)]
__device__ float     g_e2[NK];
__device__ int       g_idx[NTOK];
__device__ int       g_fix[NTOK];
__device__ int       g_nfix;
__device__ unsigned  g_cnt[NK];
__device__ double    g_sum;

__device__ __forceinline__ unsigned f2tf32(float v) {
    unsigned u;
    asm("cvt.rna.tf32.f32 %0, %1;" : "=r"(u) : "f"(v));
    return u;
}
__device__ __forceinline__ void mma_tf32(float* c, unsigned a0, unsigned a1,
                                         unsigned a2, unsigned a3,
                                         unsigned b0, unsigned b1) {
    asm volatile(
        "mma.sync.aligned.m16n8k8.row.col.f32.tf32.tf32.f32 "
        "{%0,%1,%2,%3}, {%4,%5,%6,%7}, {%8,%9}, {%0,%1,%2,%3};"
        : "+f"(c[0]), "+f"(c[1]), "+f"(c[2]), "+f"(c[3])
        : "r"(a0), "r"(a1), "r"(a2), "r"(a3), "r"(b0), "r"(b1));
}
// k-pair permutation: within each 8-wide k group, col (c, c+4) -> (2c, 2c+1)
__device__ __forceinline__ int permd(int d) {
    return (d & 0x38) + ((d & 3) << 1) + ((d >> 2) & 1);
}

// ===================== Kernel: prep embedding =====================
__global__ void k_prep_emb(const float* __restrict__ emb) {
    int k = threadIdx.x;              // 512 threads
    if (k == 0) { g_sum = 0.0; g_nfix = 0; }
    g_cnt[k] = 0u;
    const float* e = emb + k * ND;
    float s = 0.f;
#pragma unroll
    for (int d = 0; d < ND; d++) {
        float v = e[d];
        s = __fadd_rn(s, __fmul_rn(v, v));
        g_et32[k * ND + permd(d)] = f2tf32(v);
    }
    g_e2[k] = s;
}

// ===================== Kernel: tf32 screening with certainty test =====
// CTA = 256 threads (8 warps), 128 tokens. Warp w owns m-tile rows
// [16w,16w+16). 16 chunks of 32 codes. Epilogue tracks best1/best2/bestk
// per token; gap > THR => approx argmin == exact argmin (certain).
// Near-ties go to a worklist for exact full-scan in k_fix.
#define AS_STRIDE 72
#define SM_A   0
#define SM_B   (128 * AS_STRIDE * 4)                 // 36864
#define SM_E2  (SM_B + 32 * AS_STRIDE * 4)           // 46080
#define SM_WC  (SM_E2 + NK * 4)                      // 48128
#define SM_WB  (SM_WC + 4)
#define SM_WL  (SM_WB + 4)
#define SMEM_SZ (SM_WL + 128 * 4)                    // 48648

__global__ __launch_bounds__(256) void k_screen(const float* __restrict__ x_in) {
    extern __shared__ char smem[];
    unsigned* As  = (unsigned*)(smem + SM_A);
    unsigned* Bs  = (unsigned*)(smem + SM_B);
    float*    se2 = (float*)(smem + SM_E2);
    int*      wcnt = (int*)(smem + SM_WC);
    int*      wbase = (int*)(smem + SM_WB);
    int*      wl   = (int*)(smem + SM_WL);

    const int tid  = threadIdx.x;
    const int lane = tid & 31;
    const int wrow = (tid >> 5) * 16;
    const int tok0 = blockIdx.x * 128;
    const int b    = tok0 >> 14;
    const int hw0  = tok0 & (NHW - 1);

    if (tid == 0) *wcnt = 0;

    // stage A: transpose-read x [d][w] -> As[w][perm(d)], tf32
    const float* xb = x_in + (size_t)b * (NC * NHW) + hw0;
    for (int i = tid; i < 64 * 128; i += 256) {
        int d = i >> 7, w = i & 127;
        As[w * AS_STRIDE + permd(d)] = f2tf32(xb[(size_t)d * NHW + w]);
    }
    for (int i = tid; i < NK; i += 256) se2[i] = g_e2[i];

    const int rA = wrow + (lane >> 2);      // this thread's row (and rA+8)
    const int cA = 2 * (lane & 3);

    float b1a = FLT_MAX, b2a = FLT_MAX; int k1a = 0;
    float b1b = FLT_MAX, b2b = FLT_MAX; int k1b = 0;

#pragma unroll 1
    for (int ch = 0; ch < 16; ch++) {
        __syncthreads();
        {   // stage B chunk: 32 code rows x 64 tf32 (already permuted)
            const uint4* src = (const uint4*)(g_et32 + ch * 32 * ND);
            for (int i4 = tid; i4 < 32 * 16; i4 += 256) {
                int n = i4 >> 4, c4 = (i4 & 15) * 4;
                *(uint4*)&Bs[n * AS_STRIDE + c4] = src[i4];
            }
        }
        __syncthreads();

        float acc[4][4];
#pragma unroll
        for (int nt = 0; nt < 4; nt++)
#pragma unroll
            for (int r = 0; r < 4; r++) acc[nt][r] = 0.f;

#pragma unroll
        for (int ks = 0; ks < 8; ks++) {
            uint2 alo = *(const uint2*)&As[rA * AS_STRIDE + ks * 8 + cA];
            uint2 ahi = *(const uint2*)&As[(rA + 8) * AS_STRIDE + ks * 8 + cA];
#pragma unroll
            for (int nt = 0; nt < 4; nt++) {
                uint2 bb = *(const uint2*)&Bs[(nt * 8 + (lane >> 2)) * AS_STRIDE
                                              + ks * 8 + cA];
                mma_tf32(acc[nt], alo.x, ahi.x, alo.y, ahi.y, bb.x, bb.y);
            }
        }

        // epilogue: distances d = e2 - 2*dot ; track best1/best2/bestk
#pragma unroll
        for (int nt = 0; nt < 4; nt++) {
            const int kk = ch * 32 + nt * 8 + cA;
            float2 e2p = *(const float2*)&se2[kk];
            float d00 = fmaf(-2.f, acc[nt][0], e2p.x);
            float d01 = fmaf(-2.f, acc[nt][1], e2p.y);
            float d10 = fmaf(-2.f, acc[nt][2], e2p.x);
            float d11 = fmaf(-2.f, acc[nt][3], e2p.y);
            if (d00 < b1a) { b2a = b1a; b1a = d00; k1a = kk; }
            else if (d00 < b2a) b2a = d00;
            if (d01 < b1a) { b2a = b1a; b1a = d01; k1a = kk + 1; }
            else if (d01 < b2a) b2a = d01;
            if (d10 < b1b) { b2b = b1b; b1b = d10; k1b = kk; }
            else if (d10 < b2b) b2b = d10;
            if (d11 < b1b) { b2b = b1b; b1b = d11; k1b = kk + 1; }
            else if (d11 < b2b) b2b = d11;
        }
    }

    // merge across the 4 lanes sharing each row
#pragma unroll
    for (int off = 1; off < 4; off <<= 1) {
        float o1 = __shfl_xor_sync(0xffffffffu, b1a, off);
        float o2 = __shfl_xor_sync(0xffffffffu, b2a, off);
        int   ok = __shfl_xor_sync(0xffffffffu, k1a, off);
        float nb2 = fminf(fmaxf(b1a, o1), fminf(b2a, o2));
        if (o1 < b1a || (o1 == b1a && ok < k1a)) { b1a = o1; k1a = ok; }
        b2a = nb2;
        o1 = __shfl_xor_sync(0xffffffffu, b1b, off);
        o2 = __shfl_xor_sync(0xffffffffu, b2b, off);
        ok = __shfl_xor_sync(0xffffffffu, k1b, off);
        nb2 = fminf(fmaxf(b1b, o1), fminf(b2b, o2));
        if (o1 < b1b || (o1 == b1b && ok < k1b)) { b1b = o1; k1b = ok; }
        b2b = nb2;
    }

    if ((lane & 3) == 0) {
        int tA = tok0 + rA;
        int tB = tA + 8;
        if (b2a - b1a > THR) g_idx[tA] = k1a;
        else { int p = atomicAdd(wcnt, 1); wl[p] = tA; }
        if (b2b - b1b > THR) g_idx[tB] = k1b;
        else { int p = atomicAdd(wcnt, 1); wl[p] = tB; }
    }
    __syncthreads();
    if (tid == 0) *wbase = atomicAdd(&g_nfix, *wcnt);
    __syncthreads();
    for (int i = tid; i < *wcnt; i += 256) g_fix[*wbase + i] = wl[i];
}

// ===================== Kernel: exact fix for near-tie tokens ==========
// Full exact scan per worklist token, bitwise-reference rounding:
// sequential fmaf over ascending d per code; ascending-k strict-< argmin.
__global__ __launch_bounds__(256) void k_fix(const float* __restrict__ x_in,
                                             const float* __restrict__ emb) {
    const int n = g_nfix;
    for (int i = blockIdx.x * 256 + threadIdx.x; i < n; i += gridDim.x * 256) {
        const int t  = g_fix[i];
        const int b  = t >> 14;
        const int hw = t & (NHW - 1);
        const float* xp = x_in + (size_t)b * (NC * NHW) + hw;

        float x[ND];
#pragma unroll
        for (int d = 0; d < ND; d++) x[d] = xp[(size_t)d * NHW];
        float sx = 0.f;
#pragma unroll
        for (int d = 0; d < ND; d++) sx = __fadd_rn(sx, __fmul_rn(x[d], x[d]));

        float best = FLT_MAX;
        int   bk   = 0;
        for (int k = 0; k < NK; k += 4) {
            const float4* e0r = (const float4*)(emb + (size_t)(k + 0) * ND);
            const float4* e1r = (const float4*)(emb + (size_t)(k + 1) * ND);
            const float4* e2r = (const float4*)(emb + (size_t)(k + 2) * ND);
            const float4* e3r = (const float4*)(emb + (size_t)(k + 3) * ND);
            float dot0 = 0.f, dot1 = 0.f, dot2 = 0.f, dot3 = 0.f;
#pragma unroll
            for (int j = 0; j < 16; j++) {
                float4 e0 = e0r[j], e1 = e1r[j], e2 = e2r[j], e3 = e3r[j];
                float x0 = x[4 * j + 0], x1 = x[4 * j + 1];
                float x2 = x[4 * j + 2], x3 = x[4 * j + 3];
                dot0 = fmaf(x0, e0.x, dot0); dot1 = fmaf(x0, e1.x, dot1);
                dot2 = fmaf(x0, e2.x, dot2); dot3 = fmaf(x0, e3.x, dot3);
                dot0 = fmaf(x1, e0.y, dot0); dot1 = fmaf(x1, e1.y, dot1);
                dot2 = fmaf(x1, e2.y, dot2); dot3 = fmaf(x1, e3.y, dot3);
                dot0 = fmaf(x2, e0.z, dot0); dot1 = fmaf(x2, e1.z, dot1);
                dot2 = fmaf(x2, e2.z, dot2); dot3 = fmaf(x2, e3.z, dot3);
                dot0 = fmaf(x3, e0.w, dot0); dot1 = fmaf(x3, e1.w, dot1);
                dot2 = fmaf(x3, e2.w, dot2); dot3 = fmaf(x3, e3.w, dot3);
            }
            float dd0 = __fsub_rn(__fadd_rn(sx, g_e2[k + 0]), 2.0f * dot0);
            float dd1 = __fsub_rn(__fadd_rn(sx, g_e2[k + 1]), 2.0f * dot1);
            float dd2 = __fsub_rn(__fadd_rn(sx, g_e2[k + 2]), 2.0f * dot2);
            float dd3 = __fsub_rn(__fadd_rn(sx, g_e2[k + 3]), 2.0f * dot3);
            if (dd0 < best) { best = dd0; bk = k + 0; }
            if (dd1 < best) { best = dd1; bk = k + 1; }
            if (dd2 < best) { best = dd2; bk = k + 2; }
            if (dd3 < best) { best = dd3; bk = k + 3; }
        }
        g_idx[t] = bk;
    }
}

// ===================== Kernel: quantize + loss =====================
__global__ __launch_bounds__(256) void k_quant(const float* __restrict__ x_in,
                                               const float* __restrict__ emb,
                                               float* __restrict__ out) {
    __shared__ float sq[128 * 65];
    __shared__ int   sidx[128];
    __shared__ float spart[8];

    const int tid = threadIdx.x;
    const int bh  = blockIdx.x;
    const int b   = bh >> 7;
    const int h   = bh & 127;

    if (tid < 128) sidx[tid] = g_idx[b * NHW + h * NW + tid];
    __syncthreads();

    for (int i = tid; i < 128 * ND; i += 256) {
        int w = i >> 6, d = i & 63;
        sq[w * 65 + d] = emb[(size_t)sidx[w] * ND + d];
    }
    __syncthreads();

    const float* xb = x_in + (size_t)b * NC * NHW + h * NW;
    float*       qb = out + OFF_Q + (size_t)b * NC * NHW + h * NW;

    float ls = 0.f;
    for (int i = tid; i < NC * NW; i += 256) {
        int c = i >> 7, w = i & 127;
        float q  = sq[w * 65 + c];
        float xv = xb[(size_t)c * NHW + w];
        float dd = q - xv;
        ls += dd * dd;
        qb[(size_t)c * NHW + w] = q;
    }

    for (int o = 16; o; o >>= 1) ls += __shfl_xor_sync(0xffffffffu, ls, o);
    if ((tid & 31) == 0) spart[tid >> 5] = ls;
    __syncthreads();
    if (tid == 0) {
        float s = 0.f;
        for (int i = 0; i < 8; i++) s += spart[i];
        atomicAdd(&g_sum, (double)s);
    }
}

// ===================== Kernel: zero-fill encodings =====================
__global__ __launch_bounds__(256) void k_enc_zero(float* __restrict__ out) {
    const long long gid = (long long)blockIdx.x * 256 + threadIdx.x;
    float* base = out + OFF_ENC + 2;
    const float4 z = make_float4(0.f, 0.f, 0.f, 0.f);
    long long s0 = gid * 4;
#pragma unroll
    for (int u = 0; u < 4; u++) {
        long long s = s0 + u;
        if (s < ENC_V4) *(float4*)(base + 4 * s) = z;
    }
    if (gid == 0) {
        out[OFF_ENC + 0] = 0.f;
        out[OFF_ENC + 1] = 0.f;
        out[OFF_ENC + ENC_F - 2] = 0.f;
        out[OFF_ENC + ENC_F - 1] = 0.f;
    }
}

// ===================== Kernel: ones + histogram =====================
__global__ __launch_bounds__(256) void k_enc_one(float* __restrict__ out) {
    __shared__ unsigned scnt[NK];
    const int tid = threadIdx.x;
    const int t   = blockIdx.x * 256 + tid;
    for (int i = tid; i < NK; i += 256) scnt[i] = 0u;
    __syncthreads();
    const int id = g_idx[t];
    out[OFF_ENC + (size_t)t * NK + id] = 1.f;
    atomicAdd(&scnt[id], 1u);
    __syncthreads();
    for (int i = tid; i < NK; i += 256)
        if (scnt[i]) atomicAdd(&g_cnt[i], scnt[i]);
}

// ===================== Kernel: scalars =====================
__global__ void k_final(float* __restrict__ out) {
    __shared__ double sh[NK];
    const int k = threadIdx.x;
    double p = (double)g_cnt[k] / (double)NTOK;
    sh[k] = p * log(p + 1e-10);
    __syncthreads();
    for (int s = 256; s; s >>= 1) {
        if (k < s) sh[k] += sh[k + s];
        __syncthreads();
    }
    if (k == 0) {
        out[OFF_PERP] = (float)exp(-sh[0]);
        out[OFF_LOSS] = (float)(1.25 * g_sum / (double)QELEMS);
    }
}

// ===================== host =====================
extern "C" void kernel_launch(void* const* d_in, const int* in_sizes, int n_in,
                              void* d_out, int out_size) {
    const float* p0 = (const float*)d_in[0];
    const float* p1 = (const float*)d_in[1];
    const float* x_in;
    const float* emb;
    if (in_sizes[0] == NK * ND) { emb = p0; x_in = p1; }
    else                        { x_in = p0; emb = p1; }
    float* out = (float*)d_out;

    cudaFuncSetAttribute(k_screen, cudaFuncAttributeMaxDynamicSharedMemorySize,
                         SMEM_SZ);

    k_prep_emb<<<1, NK>>>(emb);
    k_screen  <<<NTOK / 128, 256, SMEM_SZ>>>(x_in);
    k_fix     <<<512, 256>>>(x_in, emb);
    k_quant   <<<NB * NH, 256>>>(x_in, emb, out);
    k_enc_zero<<<(int)((ENC_V4 + 1023) / 1024), 256>>>(out);
    k_enc_one <<<NTOK / 256, 256>>>(out);
    k_final   <<<1, NK>>>(out);
}

// round 12
// speedup vs baseline: 1.3333x; 1.3333x over previous
#include <cuda_runtime.h>
#include <cuda_bf16.h>
#include <math.h>
#include <stdint.h>
#include <float.h>

#define NB 16
#define NC 64
#define NH 128
#define NW 128
#define NK 512
#define ND 64
#define NHW (NH*NW)            // 16384
#define NTOK (NB*NHW)          // 262144
#define QELEMS (NB*NC*NHW)     // 1048576
#define OFF_LOSS 0
#define OFF_Q 1
#define OFF_PERP (1 + QELEMS)
#define OFF_ENC (2 + QELEMS)
#define ENC_F ((long long)NTOK * NK)
#define ENC_V4 ((ENC_F - 4) / 4)

#define TAU 1.2e-4f   // certainty gap: > 2*ulp(sx+e2) + split-bf16 dot err, with margin

__device__ unsigned  g_ebhi[NK * 32];   // bf16-pair packed emb hi [code][32]
__device__ unsigned  g_eblo[NK * 32];   // bf16-pair packed emb lo
__device__ float     g_e2[NK];
__device__ int       g_idx[NTOK];
__device__ int       g_fix[NTOK];
__device__ int       g_nfix;
__device__ unsigned  g_cnt[NK];
__device__ double    g_sum;

__device__ __forceinline__ uint32_t smem_u32(const void* p) {
    uint32_t a;
    asm("{ .reg .u64 t; cvta.to.shared.u64 t, %1; cvt.u32.u64 %0, t; }"
        : "=r"(a) : "l"(p));
    return a;
}
__device__ __forceinline__ void ldsm4(uint32_t* r, uint32_t addr) {
    asm volatile("ldmatrix.sync.aligned.m8n8.x4.shared.b16 {%0,%1,%2,%3}, [%4];"
                 : "=r"(r[0]), "=r"(r[1]), "=r"(r[2]), "=r"(r[3]) : "r"(addr));
}
__device__ __forceinline__ void mma_bf16(float* c, const uint32_t* a,
                                         const uint32_t b0, const uint32_t b1) {
    asm volatile(
        "mma.sync.aligned.m16n8k16.row.col.f32.bf16.bf16.f32 "
        "{%0,%1,%2,%3}, {%4,%5,%6,%7}, {%8,%9}, {%0,%1,%2,%3};"
        : "+f"(c[0]), "+f"(c[1]), "+f"(c[2]), "+f"(c[3])
        : "r"(a[0]), "r"(a[1]), "r"(a[2]), "r"(a[3]), "r"(b0), "r"(b1));
}
__device__ __forceinline__ unsigned pack_bf16(float a, float b) {
    unsigned short ha = __bfloat16_as_ushort(__float2bfloat16(a));
    unsigned short hb = __bfloat16_as_ushort(__float2bfloat16(b));
    return (unsigned)ha | ((unsigned)hb << 16);
}

// ===================== Kernel: prep embedding (hi/lo split) ============
__global__ void k_prep_emb(const float* __restrict__ emb) {
    int k = threadIdx.x;              // 512 threads
    if (k == 0) { g_sum = 0.0; g_nfix = 0; }
    g_cnt[k] = 0u;
    const float* e = emb + k * ND;
    float s = 0.f;
#pragma unroll
    for (int j = 0; j < 32; j++) {
        float v0 = e[2 * j], v1 = e[2 * j + 1];
        s = __fadd_rn(s, __fmul_rn(v0, v0));
        s = __fadd_rn(s, __fmul_rn(v1, v1));
        __nv_bfloat16 h0 = __float2bfloat16(v0);
        __nv_bfloat16 h1 = __float2bfloat16(v1);
        float l0 = v0 - __bfloat162float(h0);
        float l1 = v1 - __bfloat162float(h1);
        g_ebhi[k * 32 + j] = (unsigned)__bfloat16_as_ushort(h0)
                           | ((unsigned)__bfloat16_as_ushort(h1) << 16);
        g_eblo[k * 32 + j] = pack_bf16(l0, l1);
    }
    g_e2[k] = s;
}

// ===================== Kernel: split-bf16 mma screening ================
// CTA = 256 threads (8 warps), 128 tokens. Warp w owns rows [16w,16w+16).
// 8 chunks of 64 codes; per chunk 3 MMA products (hi*hi + hi*lo + lo*hi)
// give dot error ~2e-6. Register epilogue: best1/best2/argmin per row;
// gap > TAU => certain; else token goes to global fix worklist.
#define A_STRIDE 144
#define SM_AH  0
#define SM_AL  (128 * A_STRIDE)            // 18432
#define SM_BH  (2 * 128 * A_STRIDE)        // 36864
#define SM_BL  (SM_BH + 64 * A_STRIDE)     // 46080
#define SM_E2  (SM_BL + 64 * A_STRIDE)     // 55296
#define SMEM_SZ (SM_E2 + NK * 4)           // 57344

__global__ __launch_bounds__(256) void k_screen(const float* __restrict__ x_in) {
    extern __shared__ char smem[];
    float* se2 = (float*)(smem + SM_E2);

    const int tid  = threadIdx.x;
    const int wid  = tid >> 5;
    const int lane = tid & 31;
    const int tok0 = blockIdx.x * 128;
    const int b    = tok0 >> 14;
    const int hw0  = tok0 & (NHW - 1);

    // stage A hi/lo: token rows [w][d], bf16 pairs; coalesced transpose reads
    {
        const float* xb = x_in + (size_t)b * (NC * NHW) + hw0;
        const int w    = tid & 127;
        const int half = tid >> 7;           // 0: d2 0..15, 1: d2 16..31
#pragma unroll
        for (int j = 0; j < 16; j++) {
            int d2 = half * 16 + j;
            float v0 = xb[(size_t)(2 * d2) * NHW + w];
            float v1 = xb[(size_t)(2 * d2 + 1) * NHW + w];
            __nv_bfloat16 h0 = __float2bfloat16(v0);
            __nv_bfloat16 h1 = __float2bfloat16(v1);
            float l0 = v0 - __bfloat162float(h0);
            float l1 = v1 - __bfloat162float(h1);
            *(unsigned*)(smem + SM_AH + w * A_STRIDE + d2 * 4) =
                (unsigned)__bfloat16_as_ushort(h0)
                | ((unsigned)__bfloat16_as_ushort(h1) << 16);
            *(unsigned*)(smem + SM_AL + w * A_STRIDE + d2 * 4) = pack_bf16(l0, l1);
        }
    }
    for (int i = tid; i < NK; i += 256) se2[i] = g_e2[i];

    const uint32_t aHB = smem_u32(smem + SM_AH);
    const uint32_t aLB = smem_u32(smem + SM_AL);
    const uint32_t bHB = smem_u32(smem + SM_BH);
    const uint32_t bLB = smem_u32(smem + SM_BL);

    // verified R8 fragment addressing (per-lane)
    const int arow = wid * 16 + (lane & 7) + ((lane >> 3) & 1) * 8;
    const int abyt = (lane >> 4) * 16;
    const int brow = ((lane >> 4) & 1) * 8 + (lane & 7);
    const int bbyt = ((lane >> 3) & 1) * 16;

    // best tracking for this thread's two rows: rA and rA+8
    float b1a = FLT_MAX, b2a = FLT_MAX; int k1a = 0;
    float b1b = FLT_MAX, b2b = FLT_MAX; int k1b = 0;

#pragma unroll 1
    for (int ch = 0; ch < 8; ch++) {
        __syncthreads();
        {   // stage B chunk hi/lo: 64 code rows x 128B each
            const uint4* sh = (const uint4*)(g_ebhi + (size_t)ch * 64 * 32);
            const uint4* sl = (const uint4*)(g_eblo + (size_t)ch * 64 * 32);
            for (int i = tid; i < 64 * 8; i += 256) {
                int r = i >> 3, s = i & 7;
                *(uint4*)(smem + SM_BH + r * A_STRIDE + s * 16) = sh[i];
                *(uint4*)(smem + SM_BL + r * A_STRIDE + s * 16) = sl[i];
            }
        }
        __syncthreads();

        uint32_t ah[4][4], al[4][4];
#pragma unroll
        for (int ks = 0; ks < 4; ks++) {
            ldsm4(ah[ks], aHB + arow * A_STRIDE + ks * 32 + abyt);
            ldsm4(al[ks], aLB + arow * A_STRIDE + ks * 32 + abyt);
        }

        float c[8][4];
#pragma unroll
        for (int nt = 0; nt < 8; nt++)
#pragma unroll
            for (int r = 0; r < 4; r++) c[nt][r] = 0.f;

#pragma unroll
        for (int np = 0; np < 4; np++) {
#pragma unroll
            for (int ks = 0; ks < 4; ks++) {
                uint32_t bh[4], bl[4];
                ldsm4(bh, bHB + (np * 16 + brow) * A_STRIDE + ks * 32 + bbyt);
                ldsm4(bl, bLB + (np * 16 + brow) * A_STRIDE + ks * 32 + bbyt);
                mma_bf16(c[2 * np + 0], ah[ks], bh[0], bh[1]);
                mma_bf16(c[2 * np + 1], ah[ks], bh[2], bh[3]);
                mma_bf16(c[2 * np + 0], ah[ks], bl[0], bl[1]);
                mma_bf16(c[2 * np + 1], ah[ks], bl[2], bl[3]);
                mma_bf16(c[2 * np + 0], al[ks], bh[0], bh[1]);
                mma_bf16(c[2 * np + 1], al[ks], bh[2], bh[3]);
            }
        }

        // epilogue: screening score s = e2 - 2*dot (sx is token-constant)
#pragma unroll
        for (int nt = 0; nt < 8; nt++) {
            const int kk = ch * 64 + nt * 8 + 2 * (lane & 3);
            float2 e2p = *(const float2*)&se2[kk];
            float d0 = fmaf(-2.f, c[nt][0], e2p.x);
            float d1 = fmaf(-2.f, c[nt][1], e2p.y);
            float d2 = fmaf(-2.f, c[nt][2], e2p.x);
            float d3 = fmaf(-2.f, c[nt][3], e2p.y);
            if (d0 < b1a) { b2a = b1a; b1a = d0; k1a = kk; }
            else           b2a = fminf(b2a, d0);
            if (d1 < b1a) { b2a = b1a; b1a = d1; k1a = kk + 1; }
            else           b2a = fminf(b2a, d1);
            if (d2 < b1b) { b2b = b1b; b1b = d2; k1b = kk; }
            else           b2b = fminf(b2b, d2);
            if (d3 < b1b) { b2b = b1b; b1b = d3; k1b = kk + 1; }
            else           b2b = fminf(b2b, d3);
        }
    }

    // merge across the 4 lanes of each quad (they share the same rows)
#pragma unroll
    for (int off = 1; off < 4; off <<= 1) {
        float o1 = __shfl_xor_sync(0xffffffffu, b1a, off);
        float o2 = __shfl_xor_sync(0xffffffffu, b2a, off);
        int   ok = __shfl_xor_sync(0xffffffffu, k1a, off);
        float n2 = fminf(fmaxf(b1a, o1), fminf(b2a, o2));
        if (o1 < b1a || (o1 == b1a && ok < k1a)) { b1a = o1; k1a = ok; }
        b2a = n2;
        o1 = __shfl_xor_sync(0xffffffffu, b1b, off);
        o2 = __shfl_xor_sync(0xffffffffu, b2b, off);
        ok = __shfl_xor_sync(0xffffffffu, k1b, off);
        n2 = fminf(fmaxf(b1b, o1), fminf(b2b, o2));
        if (o1 < b1b || (o1 == b1b && ok < k1b)) { b1b = o1; k1b = ok; }
        b2b = n2;
    }

    if ((lane & 3) == 0) {
        const int rA = wid * 16 + (lane >> 2);
        const int tA = tok0 + rA;
        const int tB = tA + 8;
        if (b2a - b1a > TAU) g_idx[tA] = k1a;
        else { int p = atomicAdd(&g_nfix, 1); g_fix[p] = tA; }
        if (b2b - b1b > TAU) g_idx[tB] = k1b;
        else { int p = atomicAdd(&g_nfix, 1); g_fix[p] = tB; }
    }
}

// ===================== Kernel: exact fix for uncertain tokens ==========
// Full exact scan, bitwise-reference rounding: sequential fmaf over
// ascending d per code; ascending-k strict-< argmin (first-occurrence).
__global__ __launch_bounds__(256) void k_fix(const float* __restrict__ x_in,
                                             const float* __restrict__ emb) {
    const int n = g_nfix;
    for (int i = blockIdx.x * 256 + threadIdx.x; i < n; i += gridDim.x * 256) {
        const int t  = g_fix[i];
        const int b  = t >> 14;
        const int hw = t & (NHW - 1);
        const float* xp = x_in + (size_t)b * (NC * NHW) + hw;

        float x[ND];
#pragma unroll
        for (int d = 0; d < ND; d++) x[d] = xp[(size_t)d * NHW];
        float sx = 0.f;
#pragma unroll
        for (int d = 0; d < ND; d++) sx = __fadd_rn(sx, __fmul_rn(x[d], x[d]));

        float best = FLT_MAX;
        int   bk   = 0;
        for (int k = 0; k < NK; k += 4) {
            const float4* e0r = (const float4*)(emb + (size_t)(k + 0) * ND);
            const float4* e1r = (const float4*)(emb + (size_t)(k + 1) * ND);
            const float4* e2r = (const float4*)(emb + (size_t)(k + 2) * ND);
            const float4* e3r = (const float4*)(emb + (size_t)(k + 3) * ND);
            float dot0 = 0.f, dot1 = 0.f, dot2 = 0.f, dot3 = 0.f;
#pragma unroll
            for (int j = 0; j < 16; j++) {
                float4 e0 = e0r[j], e1 = e1r[j], e2 = e2r[j], e3 = e3r[j];
                float x0 = x[4 * j + 0], x1 = x[4 * j + 1];
                float x2 = x[4 * j + 2], x3 = x[4 * j + 3];
                dot0 = fmaf(x0, e0.x, dot0); dot1 = fmaf(x0, e1.x, dot1);
                dot2 = fmaf(x0, e2.x, dot2); dot3 = fmaf(x0, e3.x, dot3);
                dot0 = fmaf(x1, e0.y, dot0); dot1 = fmaf(x1, e1.y, dot1);
                dot2 = fmaf(x1, e2.y, dot2); dot3 = fmaf(x1, e3.y, dot3);
                dot0 = fmaf(x2, e0.z, dot0); dot1 = fmaf(x2, e1.z, dot1);
                dot2 = fmaf(x2, e2.z, dot2); dot3 = fmaf(x2, e3.z, dot3);
                dot0 = fmaf(x3, e0.w, dot0); dot1 = fmaf(x3, e1.w, dot1);
                dot2 = fmaf(x3, e2.w, dot2); dot3 = fmaf(x3, e3.w, dot3);
            }
            float dd0 = __fsub_rn(__fadd_rn(sx, g_e2[k + 0]), 2.0f * dot0);
            float dd1 = __fsub_rn(__fadd_rn(sx, g_e2[k + 1]), 2.0f * dot1);
            float dd2 = __fsub_rn(__fadd_rn(sx, g_e2[k + 2]), 2.0f * dot2);
            float dd3 = __fsub_rn(__fadd_rn(sx, g_e2[k + 3]), 2.0f * dot3);
            if (dd0 < best) { best = dd0; bk = k + 0; }
            if (dd1 < best) { best = dd1; bk = k + 1; }
            if (dd2 < best) { best = dd2; bk = k + 2; }
            if (dd3 < best) { best = dd3; bk = k + 3; }
        }
        g_idx[t] = bk;
    }
}

// ===================== Kernel: quantize + loss =====================
__global__ __launch_bounds__(256) void k_quant(const float* __restrict__ x_in,
                                               const float* __restrict__ emb,
                                               float* __restrict__ out) {
    __shared__ float sq[128 * 65];
    __shared__ int   sidx[128];
    __shared__ float spart[8];

    const int tid = threadIdx.x;
    const int bh  = blockIdx.x;
    const int b   = bh >> 7;
    const int h   = bh & 127;

    if (tid < 128) sidx[tid] = g_idx[b * NHW + h * NW + tid];
    __syncthreads();

    for (int i = tid; i < 128 * ND; i += 256) {
        int w = i >> 6, d = i & 63;
        sq[w * 65 + d] = emb[(size_t)sidx[w] * ND + d];
    }
    __syncthreads();

    const float* xb = x_in + (size_t)b * NC * NHW + h * NW;
    float*       qb = out + OFF_Q + (size_t)b * NC * NHW + h * NW;

    float ls = 0.f;
    for (int i = tid; i < NC * NW; i += 256) {
        int c = i >> 7, w = i & 127;
        float q  = sq[w * 65 + c];
        float xv = xb[(size_t)c * NHW + w];
        float dd = q - xv;
        ls += dd * dd;
        qb[(size_t)c * NHW + w] = q;
    }

    for (int o = 16; o; o >>= 1) ls += __shfl_xor_sync(0xffffffffu, ls, o);
    if ((tid & 31) == 0) spart[tid >> 5] = ls;
    __syncthreads();
    if (tid == 0) {
        float s = 0.f;
        for (int i = 0; i < 8; i++) s += spart[i];
        atomicAdd(&g_sum, (double)s);
    }
}

// ===================== Kernel: zero-fill encodings =====================
__global__ __launch_bounds__(256) void k_enc_zero(float* __restrict__ out) {
    const long long gid = (long long)blockIdx.x * 256 + threadIdx.x;
    float* base = out + OFF_ENC + 2;
    const float4 z = make_float4(0.f, 0.f, 0.f, 0.f);
    long long s0 = gid * 4;
#pragma unroll
    for (int u = 0; u < 4; u++) {
        long long s = s0 + u;
        if (s < ENC_V4) *(float4*)(base + 4 * s) = z;
    }
    if (gid == 0) {
        out[OFF_ENC + 0] = 0.f;
        out[OFF_ENC + 1] = 0.f;
        out[OFF_ENC + ENC_F - 2] = 0.f;
        out[OFF_ENC + ENC_F - 1] = 0.f;
    }
}

// ===================== Kernel: ones + histogram =====================
__global__ __launch_bounds__(256) void k_enc_one(float* __restrict__ out) {
    __shared__ unsigned scnt[NK];
    const int tid = threadIdx.x;
    const int t   = blockIdx.x * 256 + tid;
    for (int i = tid; i < NK; i += 256) scnt[i] = 0u;
    __syncthreads();
    const int id = g_idx[t];
    out[OFF_ENC + (size_t)t * NK + id] = 1.f;
    atomicAdd(&scnt[id], 1u);
    __syncthreads();
    for (int i = tid; i < NK; i += 256)
        if (scnt[i]) atomicAdd(&g_cnt[i], scnt[i]);
}

// ===================== Kernel: scalars =====================
__global__ void k_final(float* __restrict__ out) {
    __shared__ double sh[NK];
    const int k = threadIdx.x;
    double p = (double)g_cnt[k] / (double)NTOK;
    sh[k] = p * log(p + 1e-10);
    __syncthreads();
    for (int s = 256; s; s >>= 1) {
        if (k < s) sh[k] += sh[k + s];
        __syncthreads();
    }
    if (k == 0) {
        out[OFF_PERP] = (float)exp(-sh[0]);
        out[OFF_LOSS] = (float)(1.25 * g_sum / (double)QELEMS);
    }
}

// ===================== host =====================
extern "C" void kernel_launch(void* const* d_in, const int* in_sizes, int n_in,
                              void* d_out, int out_size) {
    const float* p0 = (const float*)d_in[0];
    const float* p1 = (const float*)d_in[1];
    const float* x_in;
    const float* emb;
    if (in_sizes[0] == NK * ND) { emb = p0; x_in = p1; }
    else                        { x_in = p0; emb = p1; }
    float* out = (float*)d_out;

    cudaFuncSetAttribute(k_screen, cudaFuncAttributeMaxDynamicSharedMemorySize,
                         SMEM_SZ);

    k_prep_emb<<<1, NK>>>(emb);
    k_screen  <<<NTOK / 128, 256, SMEM_SZ>>>(x_in);
    k_fix     <<<512, 256>>>(x_in, emb);
    k_quant   <<<NB * NH, 256>>>(x_in, emb, out);
    k_enc_zero<<<(int)((ENC_V4 + 1023) / 1024), 256>>>(out);
    k_enc_one <<<NTOK / 256, 256>>>(out);
    k_final   <<<1, NK>>>(out);
}

// round 13
// speedup vs baseline: 2.1133x; 1.5850x over previous
#include <cuda_runtime.h>
#include <cuda_bf16.h>
#include <math.h>
#include <stdint.h>
#include <float.h>

#define NB 16
#define NC 64
#define NH 128
#define NW 128
#define NK 512
#define ND 64
#define NHW (NH*NW)            // 16384
#define NTOK (NB*NHW)          // 262144
#define QELEMS (NB*NC*NHW)     // 1048576
#define OFF_LOSS 0
#define OFF_Q 1
#define OFF_PERP (1 + QELEMS)
#define OFF_ENC (2 + QELEMS)
#define ENC_F ((long long)NTOK * NK)
#define ENC_V4 ((ENC_F - 4) / 4)

#define CAND_MAX 24
#define TAU 4e-3f   // candidate slack AND certainty gap (> 2x bf16 dist err 1.5e-3)

__device__ unsigned  g_eb16[NK * 32];   // bf16-pair packed emb [code][32]
__device__ float     g_e2[NK];
__device__ short     g_cand[NTOK * CAND_MAX];
__device__ int       g_ccnt[NTOK];
__device__ int       g_idx[NTOK];
__device__ int       g_fix[NTOK];
__device__ int       g_nfix;
__device__ unsigned  g_cnt[NK];
__device__ double    g_sum;

__device__ __forceinline__ uint32_t smem_u32(const void* p) {
    uint32_t a;
    asm("{ .reg .u64 t; cvta.to.shared.u64 t, %1; cvt.u32.u64 %0, t; }"
        : "=r"(a) : "l"(p));
    return a;
}
__device__ __forceinline__ void ldsm4(uint32_t* r, uint32_t addr) {
    asm volatile("ldmatrix.sync.aligned.m8n8.x4.shared.b16 {%0,%1,%2,%3}, [%4];"
                 : "=r"(r[0]), "=r"(r[1]), "=r"(r[2]), "=r"(r[3]) : "r"(addr));
}
__device__ __forceinline__ void mma_bf16(float* c, const uint32_t* a,
                                         const uint32_t b0, const uint32_t b1) {
    asm volatile(
        "mma.sync.aligned.m16n8k16.row.col.f32.bf16.bf16.f32 "
        "{%0,%1,%2,%3}, {%4,%5,%6,%7}, {%8,%9}, {%0,%1,%2,%3};"
        : "+f"(c[0]), "+f"(c[1]), "+f"(c[2]), "+f"(c[3])
        : "r"(a[0]), "r"(a[1]), "r"(a[2]), "r"(a[3]), "r"(b0), "r"(b1));
}
__device__ __forceinline__ unsigned pack_bf16(float a, float b) {
    unsigned short ha = __bfloat16_as_ushort(__float2bfloat16(a));
    unsigned short hb = __bfloat16_as_ushort(__float2bfloat16(b));
    return (unsigned)ha | ((unsigned)hb << 16);
}

// ===================== Kernel: prep embedding =====================
__global__ void k_prep_emb(const float* __restrict__ emb) {
    int k = threadIdx.x;              // 512 threads
    if (k == 0) { g_sum = 0.0; g_nfix = 0; }
    g_cnt[k] = 0u;
    const float* e = emb + k * ND;
    float s = 0.f;
#pragma unroll
    for (int j = 0; j < 32; j++) {
        float v0 = e[2 * j], v1 = e[2 * j + 1];
        s = __fadd_rn(s, __fmul_rn(v0, v0));
        s = __fadd_rn(s, __fmul_rn(v1, v1));
        g_eb16[k * 32 + j] = pack_bf16(v0, v1);
    }
    g_e2[k] = s;
}

// ===================== Kernel: 1x bf16 mma screening ==================
// CTA = 128 threads (4 warps), 128 tokens — the R8-verified configuration.
// Screen score s = e2 - 2*dot (sx token-constant, irrelevant for argmin/gap).
// Per token: capture candidates within running-min + TAU; track best1/best2.
// gap > TAU  => approx argmin == exact argmin (certain).
// gap <= TAU => push token to fix worklist (exact compare of candidates).
#define A_STRIDE 144
#define B_STRIDE 144
#define D_STRIDE 72
#define SM_A     0
#define SM_B     (128 * A_STRIDE)                    // 18432
#define SM_D     (SM_B + 64 * B_STRIDE)              // 27648
#define SM_E2    (SM_D + 128 * D_STRIDE * 4)         // 64512
#define SMEM_SZ  (SM_E2 + NK * 4)                    // 66560

__global__ __launch_bounds__(128) void k_screen(const float* __restrict__ x_in) {
    extern __shared__ char smem[];
    float* sD  = (float*)(smem + SM_D);
    float* se2 = (float*)(smem + SM_E2);

    const int tid  = threadIdx.x;
    const int wid  = tid >> 5;
    const int lane = tid & 31;
    const int tok0 = blockIdx.x * 128;
    const int b    = tok0 >> 14;
    const int hw0  = tok0 & (NHW - 1);

    // stage A directly from fp32 x (transpose reads, bf16 pack) — no prep_x
    {
        const float* xb = x_in + (size_t)b * (NC * NHW) + hw0;
        const int w = tid;
#pragma unroll
        for (int j = 0; j < 32; j++) {
            float v0 = xb[(size_t)(2 * j) * NHW + w];
            float v1 = xb[(size_t)(2 * j + 1) * NHW + w];
            *(unsigned*)(smem + SM_A + w * A_STRIDE + j * 4) = pack_bf16(v0, v1);
        }
    }
    for (int i = tid; i < NK; i += 128) se2[i] = g_e2[i];

    float b1 = FLT_MAX, b2 = FLT_MAX;
    int   k1 = 0, cnt = 0;
    const size_t cbase = (size_t)(tok0 + tid) * CAND_MAX;

    const uint32_t aB = smem_u32(smem + SM_A);
    const uint32_t bB = smem_u32(smem + SM_B);

    const int arow = wid * 32 + (lane & 7) + ((lane >> 3) & 1) * 8;
    const int abyt = (lane >> 4) * 16;
    const int brow = ((lane >> 4) & 1) * 8 + (lane & 7);
    const int bbyt = ((lane >> 3) & 1) * 16;

#pragma unroll 1
    for (int ch = 0; ch < 8; ch++) {
        __syncthreads();
        {   // stage B chunk: 64 code rows x 128B
            const uint4* bs = (const uint4*)(g_eb16 + (size_t)ch * 64 * 32);
            for (int i = tid; i < 64 * 8; i += 128) {
                int r = i >> 3, s = i & 7;
                *(uint4*)(smem + SM_B + r * B_STRIDE + s * 16) = bs[i];
            }
        }
        __syncthreads();

        uint32_t a[2][4][4];
#pragma unroll
        for (int mt = 0; mt < 2; mt++)
#pragma unroll
            for (int ks = 0; ks < 4; ks++)
                ldsm4(a[mt][ks], aB + (arow + mt * 16) * A_STRIDE + ks * 32 + abyt);

        float c[2][8][4];
#pragma unroll
        for (int mt = 0; mt < 2; mt++)
#pragma unroll
            for (int nt = 0; nt < 8; nt++)
#pragma unroll
                for (int r = 0; r < 4; r++) c[mt][nt][r] = 0.f;

#pragma unroll
        for (int np = 0; np < 4; np++) {
            uint32_t bfr[4][4];
#pragma unroll
            for (int ks = 0; ks < 4; ks++)
                ldsm4(bfr[ks], bB + (np * 16 + brow) * B_STRIDE + ks * 32 + bbyt);
#pragma unroll
            for (int mt = 0; mt < 2; mt++)
#pragma unroll
                for (int ks = 0; ks < 4; ks++) {
                    mma_bf16(c[mt][2 * np + 0], a[mt][ks], bfr[ks][0], bfr[ks][1]);
                    mma_bf16(c[mt][2 * np + 1], a[mt][ks], bfr[ks][2], bfr[ks][3]);
                }
        }

        // dump dots to sD [128][72]
#pragma unroll
        for (int mt = 0; mt < 2; mt++) {
#pragma unroll
            for (int nt = 0; nt < 8; nt++) {
                int r0  = wid * 32 + mt * 16 + (lane >> 2);
                int col = nt * 8 + 2 * (lane & 3);
                *(float2*)&sD[r0 * D_STRIDE + col] =
                    make_float2(c[mt][nt][0], c[mt][nt][1]);
                *(float2*)&sD[(r0 + 8) * D_STRIDE + col] =
                    make_float2(c[mt][nt][2], c[mt][nt][3]);
            }
        }
        __syncthreads();

        // scan: thread tid owns token tok0+tid -> sD row tid
        const float* dr = sD + tid * D_STRIDE;
        const int code0 = ch * 64;
#pragma unroll
        for (int j = 0; j < 16; j++) {
            float4 f = *(const float4*)&dr[4 * j];
            const int cc = code0 + 4 * j;
            float d0 = fmaf(-2.f, f.x, se2[cc + 0]);
            float d1 = fmaf(-2.f, f.y, se2[cc + 1]);
            float d2 = fmaf(-2.f, f.z, se2[cc + 2]);
            float d3 = fmaf(-2.f, f.w, se2[cc + 3]);
            if (d0 <= b1 + TAU) { if (cnt < CAND_MAX) g_cand[cbase + cnt] = (short)(cc + 0); cnt++; }
            if (d0 < b1) { b2 = b1; b1 = d0; k1 = cc + 0; } else if (d0 < b2) b2 = d0;
            if (d1 <= b1 + TAU) { if (cnt < CAND_MAX) g_cand[cbase + cnt] = (short)(cc + 1); cnt++; }
            if (d1 < b1) { b2 = b1; b1 = d1; k1 = cc + 1; } else if (d1 < b2) b2 = d1;
            if (d2 <= b1 + TAU) { if (cnt < CAND_MAX) g_cand[cbase + cnt] = (short)(cc + 2); cnt++; }
            if (d2 < b1) { b2 = b1; b1 = d2; k1 = cc + 2; } else if (d2 < b2) b2 = d2;
            if (d3 <= b1 + TAU) { if (cnt < CAND_MAX) g_cand[cbase + cnt] = (short)(cc + 3); cnt++; }
            if (d3 < b1) { b2 = b1; b1 = d3; k1 = cc + 3; } else if (d3 < b2) b2 = d3;
        }
    }

    g_idx[tok0 + tid] = k1;        // overwritten by k_fix for uncertain tokens
    g_ccnt[tok0 + tid] = cnt;

    // CTA-aggregated fix worklist (overlay scratch on sD; scan is complete)
    __syncthreads();
    int* wl    = (int*)sD;         // [128]
    int* wcnt  = wl + 128;
    int* wbase = wl + 129;
    if (tid == 0) *wcnt = 0;
    __syncthreads();
    const int uncertain = (b2 - b1 <= TAU);
    int pos = -1;
    if (uncertain) pos = atomicAdd(wcnt, 1);
    if (pos >= 0) wl[pos] = tok0 + tid;
    __syncthreads();
    if (tid == 0) *wbase = atomicAdd(&g_nfix, *wcnt);
    __syncthreads();
    for (int i = tid; i < *wcnt; i += 128) g_fix[*wbase + i] = wl[i];
}

// ===================== Kernel: exact fix for uncertain tokens ==========
// Exact reference-rounded distances: sequential fmaf over ascending d
// (bitwise identical to the R1/R2/R8 chains that passed). Candidates are
// stored in ascending code order; tie-break smallest index.
__global__ __launch_bounds__(256) void k_fix(const float* __restrict__ x_in,
                                             const float* __restrict__ emb) {
    const int n = g_nfix;
    for (int i = blockIdx.x * 256 + threadIdx.x; i < n; i += gridDim.x * 256) {
        const int t  = g_fix[i];
        const int b  = t >> 14;
        const int hw = t & (NHW - 1);
        const float* xp = x_in + (size_t)b * (NC * NHW) + hw;

        float x[ND];
#pragma unroll
        for (int d = 0; d < ND; d++) x[d] = xp[(size_t)d * NHW];
        float sx = 0.f;
#pragma unroll
        for (int d = 0; d < ND; d++) sx = __fadd_rn(sx, __fmul_rn(x[d], x[d]));

        const int cnt = g_ccnt[t];
        float best = FLT_MAX;
        int   bk   = 0;

        if (cnt <= CAND_MAX) {
            for (int ci = 0; ci < cnt; ci++) {
                const int k = g_cand[(size_t)t * CAND_MAX + ci];
                const float4* er = (const float4*)(emb + (size_t)k * ND);
                float dot = 0.f;
#pragma unroll
                for (int j = 0; j < 16; j++) {
                    float4 e = er[j];
                    dot = fmaf(x[4 * j + 0], e.x, dot);
                    dot = fmaf(x[4 * j + 1], e.y, dot);
                    dot = fmaf(x[4 * j + 2], e.z, dot);
                    dot = fmaf(x[4 * j + 3], e.w, dot);
                }
                float dd = __fsub_rn(__fadd_rn(sx, g_e2[k]), 2.0f * dot);
                if (dd < best || (dd == best && k < bk)) { best = dd; bk = k; }
            }
        } else {   // overflow: full exact scan (ascending k, strict <)
            for (int k = 0; k < NK; k++) {
                const float4* er = (const float4*)(emb + (size_t)k * ND);
                float dot = 0.f;
#pragma unroll
                for (int j = 0; j < 16; j++) {
                    float4 e = er[j];
                    dot = fmaf(x[4 * j + 0], e.x, dot);
                    dot = fmaf(x[4 * j + 1], e.y, dot);
                    dot = fmaf(x[4 * j + 2], e.z, dot);
                    dot = fmaf(x[4 * j + 3], e.w, dot);
                }
                float dd = __fsub_rn(__fadd_rn(sx, g_e2[k]), 2.0f * dot);
                if (dd < best) { best = dd; bk = k; }
            }
        }
        g_idx[t] = bk;
    }
}

// ===================== Kernel: quantize + loss =====================
__global__ __launch_bounds__(256) void k_quant(const float* __restrict__ x_in,
                                               const float* __restrict__ emb,
                                               float* __restrict__ out) {
    __shared__ float sq[128 * 65];
    __shared__ int   sidx[128];
    __shared__ float spart[8];

    const int tid = threadIdx.x;
    const int bh  = blockIdx.x;
    const int b   = bh >> 7;
    const int h   = bh & 127;

    if (tid < 128) sidx[tid] = g_idx[b * NHW + h * NW + tid];
    __syncthreads();

    for (int i = tid; i < 128 * ND; i += 256) {
        int w = i >> 6, d = i & 63;
        sq[w * 65 + d] = emb[(size_t)sidx[w] * ND + d];
    }
    __syncthreads();

    const float* xb = x_in + (size_t)b * NC * NHW + h * NW;
    float*       qb = out + OFF_Q + (size_t)b * NC * NHW + h * NW;

    float ls = 0.f;
    for (int i = tid; i < NC * NW; i += 256) {
        int c = i >> 7, w = i & 127;
        float q  = sq[w * 65 + c];
        float xv = xb[(size_t)c * NHW + w];
        float dd = q - xv;
        ls += dd * dd;
        qb[(size_t)c * NHW + w] = q;
    }

    for (int o = 16; o; o >>= 1) ls += __shfl_xor_sync(0xffffffffu, ls, o);
    if ((tid & 31) == 0) spart[tid >> 5] = ls;
    __syncthreads();
    if (tid == 0) {
        float s = 0.f;
        for (int i = 0; i < 8; i++) s += spart[i];
        atomicAdd(&g_sum, (double)s);
    }
}

// ===================== Kernel: zero-fill encodings =====================
__global__ __launch_bounds__(256) void k_enc_zero(float* __restrict__ out) {
    const long long gid = (long long)blockIdx.x * 256 + threadIdx.x;
    float* base = out + OFF_ENC + 2;
    const float4 z = make_float4(0.f, 0.f, 0.f, 0.f);
    long long s0 = gid * 4;
#pragma unroll
    for (int u = 0; u < 4; u++) {
        long long s = s0 + u;
        if (s < ENC_V4) *(float4*)(base + 4 * s) = z;
    }
    if (gid == 0) {
        out[OFF_ENC + 0] = 0.f;
        out[OFF_ENC + 1] = 0.f;
        out[OFF_ENC + ENC_F - 2] = 0.f;
        out[OFF_ENC + ENC_F - 1] = 0.f;
    }
}

// ===================== Kernel: ones + histogram =====================
__global__ __launch_bounds__(256) void k_enc_one(float* __restrict__ out) {
    __shared__ unsigned scnt[NK];
    const int tid = threadIdx.x;
    const int t   = blockIdx.x * 256 + tid;
    for (int i = tid; i < NK; i += 256) scnt[i] = 0u;
    __syncthreads();
    const int id = g_idx[t];
    out[OFF_ENC + (size_t)t * NK + id] = 1.f;
    atomicAdd(&scnt[id], 1u);
    __syncthreads();
    for (int i = tid; i < NK; i += 256)
        if (scnt[i]) atomicAdd(&g_cnt[i], scnt[i]);
}

// ===================== Kernel: scalars =====================
__global__ void k_final(float* __restrict__ out) {
    __shared__ double sh[NK];
    const int k = threadIdx.x;
    double p = (double)g_cnt[k] / (double)NTOK;
    sh[k] = p * log(p + 1e-10);
    __syncthreads();
    for (int s = 256; s; s >>= 1) {
        if (k < s) sh[k] += sh[k + s];
        __syncthreads();
    }
    if (k == 0) {
        out[OFF_PERP] = (float)exp(-sh[0]);
        out[OFF_LOSS] = (float)(1.25 * g_sum / (double)QELEMS);
    }
}

// ===================== host =====================
extern "C" void kernel_launch(void* const* d_in, const int* in_sizes, int n_in,
                              void* d_out, int out_size) {
    const float* p0 = (const float*)d_in[0];
    const float* p1 = (const float*)d_in[1];
    const float* x_in;
    const float* emb;
    if (in_sizes[0] == NK * ND) { emb = p0; x_in = p1; }
    else                        { x_in = p0; emb = p1; }
    float* out = (float*)d_out;

    cudaFuncSetAttribute(k_screen, cudaFuncAttributeMaxDynamicSharedMemorySize,
                         SMEM_SZ);

    k_prep_emb<<<1, NK>>>(emb);
    k_screen  <<<NTOK / 128, 128, SMEM_SZ>>>(x_in);
    k_fix     <<<1024, 256>>>(x_in, emb);
    k_quant   <<<NB * NH, 256>>>(x_in, emb, out);
    k_enc_zero<<<(int)((ENC_V4 + 1023) / 1024), 256>>>(out);
    k_enc_one <<<NTOK / 256, 256>>>(out);
    k_final   <<<1, NK>>>(out);
}